// round 8
// baseline (speedup 1.0000x reference)
#include <cuda_runtime.h>
#include <cuda_fp16.h>
#include <cstdint>

#define Bsz 2048
#define Hsz 1024
#define Ktot 2048           // input K (1024) + hidden K (1024)
#define Ntot 4096           // 4 gates * 1024 (gate-interleaved bands of 32)

// ---------------- scratch (static device memory; no allocs) ----------------
__device__ unsigned short g_A[Bsz * Ktot];              // 8 MB  (fp16)
__device__ unsigned short g_B[(size_t)Ntot * Ktot];     // 16 MB (fp16, [n'][k])

// ---------------- helpers ----------------
__device__ __forceinline__ uint32_t smem_u32(const void* p) {
    uint32_t a;
    asm("{ .reg .u64 t; cvta.to.shared.u64 t, %1; cvt.u32.u64 %0, t; }" : "=r"(a) : "l"(p));
    return a;
}
__device__ __forceinline__ void cp_async16(uint32_t dst, const void* src) {
    asm volatile("cp.async.cg.shared.global [%0], [%1], 16;" :: "r"(dst), "l"(src) : "memory");
}
#define CP_COMMIT() asm volatile("cp.async.commit_group;" ::: "memory")
#define CP_WAIT1()  asm volatile("cp.async.wait_group 1;" ::: "memory")

__device__ __forceinline__ void ldsm4(uint32_t& r0, uint32_t& r1, uint32_t& r2, uint32_t& r3,
                                      uint32_t addr) {
    asm volatile("ldmatrix.sync.aligned.m8n8.x4.shared.b16 {%0,%1,%2,%3}, [%4];"
                 : "=r"(r0), "=r"(r1), "=r"(r2), "=r"(r3) : "r"(addr));
}
__device__ __forceinline__ void mma16816(float* d, const uint32_t* a, const uint32_t* b) {
    asm volatile(
        "mma.sync.aligned.m16n8k16.row.col.f32.f16.f16.f32 "
        "{%0,%1,%2,%3}, {%4,%5,%6,%7}, {%8,%9}, {%0,%1,%2,%3};"
        : "+f"(d[0]), "+f"(d[1]), "+f"(d[2]), "+f"(d[3])
        : "r"(a[0]), "r"(a[1]), "r"(a[2]), "r"(a[3]), "r"(b[0]), "r"(b[1]));
}

// ------ 1+2) merged conversion kernel ------
// blocks [0, 2048):  weight transpose+convert -> g_B [n'][k], gate-interleaved
//                    n' = (j>>3)*32 + g*8 + (j&7) for gate g, hidden col j
// blocks [2048, 4096): activations [input|hidden] -> g_A fp16 (8 floats/thread)
#define NCONVB 2048

__global__ void __launch_bounds__(256, 4)
conv_kernel(const float* __restrict__ X, const float* __restrict__ Hn,
            const float* __restrict__ wf, const float* __restrict__ wi,
            const float* __restrict__ wo, const float* __restrict__ wc,
            const float* __restrict__ uf, const float* __restrict__ ui,
            const float* __restrict__ uo, const float* __restrict__ uc) {
    const int tid = threadIdx.x;
    if (blockIdx.x < NCONVB) {
        // ---- weight transpose: 64(k) x 64(n) tile ----
        __shared__ float tile[64][65];   // [k][n]
        const float* srcs[8] = {wf, wi, wo, wc, uf, ui, uo, uc};
        const int bid = blockIdx.x;
        const int k0 = (bid & 31) * 64;         // 0..2047
        const int n0 = (bid >> 5) * 64;         // 0..4095 (gate-major)
        const int g  = n0 >> 10;
        const float* W = srcs[(k0 < Hsz ? 0 : 4) + g];
        const int kk = k0 & (Hsz - 1);
        const int nn = n0 & (Hsz - 1);

        const int tn = tid & 63;                // n within tile (load phase)
        const int t4 = tid >> 6;                // 0..3
#pragma unroll
        for (int j = 0; j < 16; ++j) {
            const int k = t4 + j * 4;
            tile[k][tn] = W[(size_t)(kk + k) * Hsz + nn + tn];
        }
        __syncthreads();

        const int tk = tid & 63;                // k within tile (store phase)
#pragma unroll
        for (int j = 0; j < 16; ++j) {
            const int nl = t4 + j * 4;          // n within tile
            const int jn = nn + nl;             // hidden col
            const int np = ((jn >> 3) << 5) + (g << 3) + (jn & 7);
            g_B[(size_t)np * Ktot + k0 + tk] =
                __half_as_ushort(__float2half_rn(tile[tk][nl]));
        }
    } else {
        // ---- activation convert: 8 floats (2 float4) per thread ----
        const int idx = (blockIdx.x - NCONVB) * 256 + tid;
        const int e0 = idx * 8;
        const int col = e0 & (Ktot - 1);
        const int row = e0 >> 11;
        const float* src = (col < Hsz) ? &X[row * Hsz + col] : &Hn[row * Hsz + col - Hsz];
#pragma unroll
        for (int p = 0; p < 2; ++p) {
            float4 v = *reinterpret_cast<const float4*>(src + p * 4);
            unsigned short h[4];
            h[0] = __half_as_ushort(__float2half_rn(v.x));
            h[1] = __half_as_ushort(__float2half_rn(v.y));
            h[2] = __half_as_ushort(__float2half_rn(v.z));
            h[3] = __half_as_ushort(__float2half_rn(v.w));
            *reinterpret_cast<uint2*>(&g_A[e0 + p * 4]) = *reinterpret_cast<uint2*>(h);
        }
    }
}

// ------ 3) mma.sync single-pass fp16 GEMM + fused LSTM epilogue ------
#define BM 128
#define BN 128
#define BK 64
#define NSTAGE 3
#define A_ST_BYTES (BM * BK * 2)               // 16384
#define STAGE_BYTES (2 * A_ST_BYTES)           // 32768
#define GEMM_SMEM (NSTAGE * STAGE_BYTES)       // 98304
#define NCHUNK 32                               // 2048 / 64

// 128-byte smem rows (8 x 16B chunks); SW128 swizzle: chunk ^= row&7.
__device__ __forceinline__ uint32_t swz(uint32_t base, int r, int c) {
    return base + r * 128 + (((uint32_t)(c ^ (r & 7))) << 4);
}
__device__ __forceinline__ float sigmoidf_(float x) { return 1.0f / (1.0f + expf(-x)); }

__global__ void __launch_bounds__(256, 2)
gemm_kernel(const float* __restrict__ Cprev, const float* __restrict__ mask,
            const float* __restrict__ b1, const float* __restrict__ b2,
            const float* __restrict__ b3, const float* __restrict__ b4,
            float* __restrict__ out) {
    extern __shared__ char smem[];
    const uint32_t sb = smem_u32(smem);
    const int tid  = threadIdx.x;
    const int wid  = tid >> 5;
    const int lane = tid & 31;
    const int wm = wid >> 2;       // 0..1  (M, 64 each)
    const int wn = wid & 3;        // 0..3  (N, 32 each)
    const int bm = blockIdx.y * BM;
    const int bn = blockIdx.x * BN;

    float acc[4][4][4];
#pragma unroll
    for (int mf = 0; mf < 4; ++mf)
#pragma unroll
        for (int nf = 0; nf < 4; ++nf)
#pragma unroll
            for (int r = 0; r < 4; ++r) acc[mf][nf][r] = 0.0f;

    const int lr = tid >> 3;          // row 0..31 (+32*i)
    const int lc = tid & 7;           // chunk col 0..7

    auto load_chunk = [&](int c, int st) {
        const uint32_t sA = sb + (uint32_t)st * STAGE_BYTES;
        const uint32_t sB = sA + A_ST_BYTES;
        const char* Ag = (const char*)g_A + ((size_t)bm * Ktot + (size_t)c * BK) * 2;
        const char* Bg = (const char*)g_B + ((size_t)bn * Ktot + (size_t)c * BK) * 2;
#pragma unroll
        for (int i = 0; i < 4; ++i) {
            const int r = lr + i * 32;
            cp_async16(swz(sA, r, lc), Ag + (size_t)r * (Ktot * 2) + lc * 16);
        }
#pragma unroll
        for (int i = 0; i < 4; ++i) {
            const int r = lr + i * 32;
            cp_async16(swz(sB, r, lc), Bg + (size_t)r * (Ktot * 2) + lc * 16);
        }
        CP_COMMIT();
    };

    load_chunk(0, 0);
    load_chunk(1, 1);

    const int a_row = wm * 64 + (lane & 15);
    const int a_cb  = (lane >> 4) & 1;
    const int b_row = wn * 32 + ((lane >> 4) & 1) * 8 + (lane & 7);
    const int b_cb  = (lane >> 3) & 1;

    int rd = 0;                        // stage holding chunk c
    for (int c = 0; c < NCHUNK; ++c) {
        CP_WAIT1();
        __syncthreads();
        if (c + 2 < NCHUNK) {
            const int wr = (rd == 0) ? 2 : rd - 1;
            load_chunk(c + 2, wr);
        } else {
            CP_COMMIT();
        }

        const uint32_t sA = sb + (uint32_t)rd * STAGE_BYTES;
        const uint32_t sB = sA + A_ST_BYTES;
#pragma unroll
        for (int ks = 0; ks < 4; ++ks) {
            uint32_t bf[2][4];
#pragma unroll
            for (int nfp = 0; nfp < 2; ++nfp)
                ldsm4(bf[nfp][0], bf[nfp][1], bf[nfp][2], bf[nfp][3],
                      swz(sB, b_row + nfp * 16, ks * 2 + b_cb));
            uint32_t af[4][4];
#pragma unroll
            for (int mf = 0; mf < 4; ++mf)
                ldsm4(af[mf][0], af[mf][1], af[mf][2], af[mf][3],
                      swz(sA, a_row + mf * 16, ks * 2 + a_cb));
#pragma unroll
            for (int mf = 0; mf < 4; ++mf)
#pragma unroll
                for (int nf = 0; nf < 4; ++nf)
                    mma16816(acc[mf][nf], af[mf], &bf[nf >> 1][(nf & 1) * 2]);
        }
        rd = (rd == 2) ? 0 : rd + 1;
    }

    // ---- fused LSTM epilogue ----
    const int grp = lane >> 2, tig = lane & 3;
    const int j0 = ((bn >> 5) + wn) * 8 + tig * 2;   // hidden col of acc pair
    const float2 B1 = *reinterpret_cast<const float2*>(&b1[j0]);
    const float2 B2 = *reinterpret_cast<const float2*>(&b2[j0]);
    const float2 B3 = *reinterpret_cast<const float2*>(&b3[j0]);
    const float2 B4 = *reinterpret_cast<const float2*>(&b4[j0]);

#pragma unroll
    for (int mf = 0; mf < 4; ++mf) {
#pragma unroll
        for (int rh = 0; rh < 2; ++rh) {
            const int row = bm + wm * 64 + mf * 16 + grp + rh * 8;
            const size_t rb = (size_t)row * Hsz + j0;
            const float2 cp = *reinterpret_cast<const float2*>(&Cprev[rb]);
            const float2 mk = *reinterpret_cast<const float2*>(&mask[rb]);
            float hv[2], cv[2];
#pragma unroll
            for (int e = 0; e < 2; ++e) {
                const int r = rh * 2 + e;
                float ft = sigmoidf_(acc[mf][0][r] + (e ? B1.y : B1.x));
                float it = sigmoidf_(acc[mf][1][r] + (e ? B2.y : B2.x));
                float ot = sigmoidf_(acc[mf][2][r] + (e ? B3.y : B3.x));
                float gt = tanhf   (acc[mf][3][r] + (e ? B4.y : B4.x));
                float ct = (e ? cp.y : cp.x) * ft + it * gt;
                hv[e] = ot * tanhf(ct) * (e ? mk.y : mk.x);
                cv[e] = ct;
            }
            *reinterpret_cast<float2*>(&out[rb]) = make_float2(hv[0], hv[1]);
            *reinterpret_cast<float2*>(&out[(size_t)Bsz * Hsz + rb]) = make_float2(cv[0], cv[1]);
        }
    }
}

// ---------------- launch ----------------
extern "C" void kernel_launch(void* const* d_in, const int* in_sizes, int n_in,
                              void* d_out, int out_size) {
    const float* X     = (const float*)d_in[0];
    const float* Hn    = (const float*)d_in[1];
    const float* Cprev = (const float*)d_in[2];
    const float* wi    = (const float*)d_in[3];
    const float* wf    = (const float*)d_in[4];
    const float* wo    = (const float*)d_in[5];
    const float* wc    = (const float*)d_in[6];
    const float* ui    = (const float*)d_in[7];
    const float* uf    = (const float*)d_in[8];
    const float* uo    = (const float*)d_in[9];
    const float* uc    = (const float*)d_in[10];
    const float* b1    = (const float*)d_in[11];
    const float* b2    = (const float*)d_in[12];
    const float* b3    = (const float*)d_in[13];
    const float* b4    = (const float*)d_in[14];
    const float* mask  = (const float*)d_in[15];
    float* out = (float*)d_out;

    // merged conversions: 2048 weight-transpose CTAs + 2048 activation CTAs
    conv_kernel<<<NCONVB + (Bsz * Ktot / 8) / 256, 256>>>(
        X, Hn, wf, wi, wo, wc, uf, ui, uo, uc);

    static bool attr_set = false;
    if (!attr_set) {
        cudaFuncSetAttribute(gemm_kernel, cudaFuncAttributeMaxDynamicSharedMemorySize, GEMM_SMEM);
        attr_set = true;
    }
    dim3 gg(Ntot / BN, Bsz / BM);      // (32, 16) = 512 CTAs
    gemm_kernel<<<gg, 256, GEMM_SMEM>>>(Cprev, mask, b1, b2, b3, b4, out);
}

// round 10
// speedup vs baseline: 1.0462x; 1.0462x over previous
#include <cuda_runtime.h>
#include <cuda_fp16.h>
#include <cstdint>

#define Bsz 2048
#define Hsz 1024
#define Ktot 2048           // input K (1024) + hidden K (1024)
#define Ntot 4096           // 4 gates * 1024 (gate-interleaved bands of 32)

// ---------------- scratch (static device memory; no allocs) ----------------
__device__ unsigned short g_A[Bsz * Ktot];              // 8 MB  (fp16)
__device__ unsigned short g_B[(size_t)Ntot * Ktot];     // 16 MB (fp16, [n'][k])

// ---------------- helpers ----------------
__device__ __forceinline__ uint32_t smem_u32(const void* p) {
    uint32_t a;
    asm("{ .reg .u64 t; cvta.to.shared.u64 t, %1; cvt.u32.u64 %0, t; }" : "=r"(a) : "l"(p));
    return a;
}
__device__ __forceinline__ void cp_async16(uint32_t dst, const void* src) {
    asm volatile("cp.async.cg.shared.global [%0], [%1], 16;" :: "r"(dst), "l"(src) : "memory");
}
#define CP_COMMIT() asm volatile("cp.async.commit_group;" ::: "memory")
#define CP_WAIT1()  asm volatile("cp.async.wait_group 1;" ::: "memory")

__device__ __forceinline__ void ldsm4(uint32_t& r0, uint32_t& r1, uint32_t& r2, uint32_t& r3,
                                      uint32_t addr) {
    asm volatile("ldmatrix.sync.aligned.m8n8.x4.shared.b16 {%0,%1,%2,%3}, [%4];"
                 : "=r"(r0), "=r"(r1), "=r"(r2), "=r"(r3) : "r"(addr));
}
__device__ __forceinline__ void mma16816(float* d, const uint32_t* a, const uint32_t* b) {
    asm volatile(
        "mma.sync.aligned.m16n8k16.row.col.f32.f16.f16.f32 "
        "{%0,%1,%2,%3}, {%4,%5,%6,%7}, {%8,%9}, {%0,%1,%2,%3};"
        : "+f"(d[0]), "+f"(d[1]), "+f"(d[2]), "+f"(d[3])
        : "r"(a[0]), "r"(a[1]), "r"(a[2]), "r"(a[3]), "r"(b[0]), "r"(b[1]));
}

// ---------------- 1) convert A: [input | hidden] -> fp16 ----------------
__global__ void conv_a_kernel(const float* __restrict__ X, const float* __restrict__ Hn) {
    int idx = blockIdx.x * blockDim.x + threadIdx.x;     // one float4
    int e0   = idx * 4;
    int col4 = e0 & (Ktot - 1);
    int row  = e0 >> 11;
    const float* src = (col4 < Hsz) ? &X[row * Hsz + col4] : &Hn[row * Hsz + col4 - Hsz];
    float4 v = *reinterpret_cast<const float4*>(src);
    unsigned short h[4];
    h[0] = __half_as_ushort(__float2half_rn(v.x));
    h[1] = __half_as_ushort(__float2half_rn(v.y));
    h[2] = __half_as_ushort(__float2half_rn(v.z));
    h[3] = __half_as_ushort(__float2half_rn(v.w));
    *reinterpret_cast<uint2*>(&g_A[e0]) = *reinterpret_cast<uint2*>(h);
}

// ------ 2) transpose + convert weights -> B [n'][k] fp16, gate-interleaved ----
// n' = (j>>3)*32 + g*8 + (j&7)   for original gate g, hidden col j
__global__ void conv_b_kernel(const float* wf, const float* wi, const float* wo, const float* wc,
                              const float* uf, const float* ui, const float* uo, const float* uc) {
    __shared__ float tile[64][65];     // [k][n]
    const float* srcs[8] = {wf, wi, wo, wc, uf, ui, uo, uc};
    int k0 = blockIdx.x * 64;          // 0..2047
    int n0 = blockIdx.y * 64;          // 0..4095 (original gate-major space)
    int g  = n0 >> 10;
    const float* W = srcs[(k0 < Hsz ? 0 : 4) + g];
    int kk = k0 & (Hsz - 1);
    int nn = n0 & (Hsz - 1);
    int tx = threadIdx.x, ty = threadIdx.y;  // 64 x 8
#pragma unroll
    for (int j = 0; j < 8; ++j)
        tile[ty + j * 8][tx] = W[(size_t)(kk + ty + j * 8) * Hsz + nn + tx];
    __syncthreads();
#pragma unroll
    for (int j = 0; j < 8; ++j) {
        int jn = nn + ty + j * 8;            // hidden col
        int np = ((jn >> 3) << 5) + (g << 3) + (jn & 7);
        g_B[(size_t)np * Ktot + k0 + tx] =
            __half_as_ushort(__float2half_rn(tile[tx][ty + j * 8]));
    }
}

// ------ 3) mma.sync fp16 GEMM, 64x64 warp tiles + fused LSTM epilogue ------
#define BM 128
#define BN 128
#define BK 64
#define NSTAGE 3
#define A_ST_BYTES (BM * BK * 2)               // 16384
#define STAGE_BYTES (2 * A_ST_BYTES)           // 32768
#define GEMM_SMEM (NSTAGE * STAGE_BYTES)       // 98304
#define NCHUNK 32                               // 2048 / 64

// 128-byte smem rows (8 x 16B chunks); SW128 swizzle: chunk ^= row&7.
__device__ __forceinline__ uint32_t swz(uint32_t base, int r, int c) {
    return base + r * 128 + (((uint32_t)(c ^ (r & 7))) << 4);
}
__device__ __forceinline__ float sigmoidf_(float x) { return 1.0f / (1.0f + expf(-x)); }

__global__ void __launch_bounds__(128, 2)
gemm_kernel(const float* __restrict__ Cprev, const float* __restrict__ mask,
            const float* __restrict__ b1, const float* __restrict__ b2,
            const float* __restrict__ b3, const float* __restrict__ b4,
            float* __restrict__ out) {
    extern __shared__ char smem[];
    const uint32_t sb = smem_u32(smem);
    const int tid  = threadIdx.x;
    const int wid  = tid >> 5;
    const int lane = tid & 31;
    const int wm = wid >> 1;       // 0..1  (M, 64 each)
    const int wn = wid & 1;        // 0..1  (N, 64 each)
    const int bm = blockIdx.y * BM;
    const int bn = blockIdx.x * BN;

    float acc[4][8][4];            // [mf][n-octet][reg] = 128 regs
#pragma unroll
    for (int mf = 0; mf < 4; ++mf)
#pragma unroll
        for (int o = 0; o < 8; ++o)
#pragma unroll
            for (int r = 0; r < 4; ++r) acc[mf][o][r] = 0.0f;

    // per-thread load map: 128 rows x 8 chunks per tensor, 128 threads -> 8 each
    const int lr = tid >> 3;          // row 0..15 (+16*i)
    const int lc = tid & 7;           // chunk col 0..7

    auto load_chunk = [&](int c, int st) {
        const uint32_t sA = sb + (uint32_t)st * STAGE_BYTES;
        const uint32_t sB = sA + A_ST_BYTES;
        const char* Ag = (const char*)g_A + ((size_t)bm * Ktot + (size_t)c * BK) * 2;
        const char* Bg = (const char*)g_B + ((size_t)bn * Ktot + (size_t)c * BK) * 2;
#pragma unroll
        for (int i = 0; i < 8; ++i) {
            const int r = lr + i * 16;
            cp_async16(swz(sA, r, lc), Ag + (size_t)r * (Ktot * 2) + lc * 16);
        }
#pragma unroll
        for (int i = 0; i < 8; ++i) {
            const int r = lr + i * 16;
            cp_async16(swz(sB, r, lc), Bg + (size_t)r * (Ktot * 2) + lc * 16);
        }
        CP_COMMIT();
    };

    load_chunk(0, 0);
    load_chunk(1, 1);

    const int a_row = wm * 64 + (lane & 15);
    const int a_cb  = (lane >> 4) & 1;
    const int b_row = wn * 64 + ((lane >> 4) & 1) * 8 + (lane & 7);
    const int b_cb  = (lane >> 3) & 1;

    int rd = 0;                        // stage holding chunk c
    for (int c = 0; c < NCHUNK; ++c) {
        CP_WAIT1();
        __syncthreads();
        if (c + 2 < NCHUNK) {
            const int wr = (rd == 0) ? 2 : rd - 1;
            load_chunk(c + 2, wr);
        } else {
            CP_COMMIT();
        }

        const uint32_t sA = sb + (uint32_t)rd * STAGE_BYTES;
        const uint32_t sB = sA + A_ST_BYTES;
#pragma unroll
        for (int ks = 0; ks < 4; ++ks) {
            uint32_t bf[4][4];         // [nfp] covers local n = nfp*16 + {0-7, 8-15}
#pragma unroll
            for (int nfp = 0; nfp < 4; ++nfp)
                ldsm4(bf[nfp][0], bf[nfp][1], bf[nfp][2], bf[nfp][3],
                      swz(sB, b_row + nfp * 16, ks * 2 + b_cb));
            uint32_t af[4][4];
#pragma unroll
            for (int mf = 0; mf < 4; ++mf)
                ldsm4(af[mf][0], af[mf][1], af[mf][2], af[mf][3],
                      swz(sA, a_row + mf * 16, ks * 2 + a_cb));
#pragma unroll
            for (int mf = 0; mf < 4; ++mf)
#pragma unroll
                for (int o = 0; o < 8; ++o)
                    mma16816(acc[mf][o], af[mf], &bf[o >> 1][(o & 1) * 2]);
        }
        rd = (rd == 2) ? 0 : rd + 1;
    }

    // ---- fused LSTM epilogue ----
    // warp N range = [bn + wn*64, +64) = 2 gate-interleaved bands of 32.
    // octet o: band b = o>>2, gate = o&3, j0 = ((bn>>5) + wn*2 + b)*8 + tig*2
    const int grp = lane >> 2, tig = lane & 3;
#pragma unroll
    for (int b = 0; b < 2; ++b) {
        const int j0 = ((bn >> 5) + wn * 2 + b) * 8 + tig * 2;
        const float2 B1 = *reinterpret_cast<const float2*>(&b1[j0]);
        const float2 B2 = *reinterpret_cast<const float2*>(&b2[j0]);
        const float2 B3 = *reinterpret_cast<const float2*>(&b3[j0]);
        const float2 B4 = *reinterpret_cast<const float2*>(&b4[j0]);
#pragma unroll
        for (int mf = 0; mf < 4; ++mf) {
#pragma unroll
            for (int rh = 0; rh < 2; ++rh) {
                const int row = bm + wm * 64 + mf * 16 + grp + rh * 8;
                const size_t rb = (size_t)row * Hsz + j0;
                const float2 cp = *reinterpret_cast<const float2*>(&Cprev[rb]);
                const float2 mk = *reinterpret_cast<const float2*>(&mask[rb]);
                float hv[2], cv[2];
#pragma unroll
                for (int e = 0; e < 2; ++e) {
                    const int r = rh * 2 + e;
                    float ft = sigmoidf_(acc[mf][b * 4 + 0][r] + (e ? B1.y : B1.x));
                    float it = sigmoidf_(acc[mf][b * 4 + 1][r] + (e ? B2.y : B2.x));
                    float ot = sigmoidf_(acc[mf][b * 4 + 2][r] + (e ? B3.y : B3.x));
                    float gt = tanhf   (acc[mf][b * 4 + 3][r] + (e ? B4.y : B4.x));
                    float ct = (e ? cp.y : cp.x) * ft + it * gt;
                    hv[e] = ot * tanhf(ct) * (e ? mk.y : mk.x);
                    cv[e] = ct;
                }
                *reinterpret_cast<float2*>(&out[rb]) = make_float2(hv[0], hv[1]);
                *reinterpret_cast<float2*>(&out[(size_t)Bsz * Hsz + rb]) = make_float2(cv[0], cv[1]);
            }
        }
    }
}

// ---------------- launch ----------------
extern "C" void kernel_launch(void* const* d_in, const int* in_sizes, int n_in,
                              void* d_out, int out_size) {
    const float* X     = (const float*)d_in[0];
    const float* Hn    = (const float*)d_in[1];
    const float* Cprev = (const float*)d_in[2];
    const float* wi    = (const float*)d_in[3];
    const float* wf    = (const float*)d_in[4];
    const float* wo    = (const float*)d_in[5];
    const float* wc    = (const float*)d_in[6];
    const float* ui    = (const float*)d_in[7];
    const float* uf    = (const float*)d_in[8];
    const float* uo    = (const float*)d_in[9];
    const float* uc    = (const float*)d_in[10];
    const float* b1    = (const float*)d_in[11];
    const float* b2    = (const float*)d_in[12];
    const float* b3    = (const float*)d_in[13];
    const float* b4    = (const float*)d_in[14];
    const float* mask  = (const float*)d_in[15];
    float* out = (float*)d_out;

    conv_a_kernel<<<(Bsz * Ktot / 4) / 256, 256>>>(X, Hn);

    dim3 tb(64, 8);
    dim3 tg(Ktot / 64, Ntot / 64);     // (32, 64)
    conv_b_kernel<<<tg, tb>>>(wf, wi, wo, wc, uf, ui, uo, uc);

    static bool attr_set = false;
    if (!attr_set) {
        cudaFuncSetAttribute(gemm_kernel, cudaFuncAttributeMaxDynamicSharedMemorySize, GEMM_SMEM);
        attr_set = true;
    }
    dim3 gg(Ntot / BN, Bsz / BM);      // (32, 16) = 512 CTAs
    gemm_kernel<<<gg, 128, GEMM_SMEM>>>(Cprev, mask, b1, b2, b3, b4, out);
}

// round 13
// speedup vs baseline: 1.1964x; 1.1435x over previous
#include <cuda_runtime.h>
#include <cuda_fp16.h>
#include <cstdint>

#define Bsz 2048
#define Hsz 1024
#define Ktot 2048           // input K (1024) + hidden K (1024)
#define Ntot 4096           // 4 gates * 1024 (gate-interleaved bands of 32)

// ---------------- scratch (static device memory; no allocs) ----------------
__device__ unsigned short g_A[Bsz * Ktot];              // 8 MB  (fp16)
__device__ unsigned short g_B[(size_t)Ntot * Ktot];     // 16 MB (fp16, [n'][k])

// ---------------- helpers ----------------
__device__ __forceinline__ uint32_t smem_u32(const void* p) {
    uint32_t a;
    asm("{ .reg .u64 t; cvta.to.shared.u64 t, %1; cvt.u32.u64 %0, t; }" : "=r"(a) : "l"(p));
    return a;
}
__device__ __forceinline__ void cp_async16(uint32_t dst, const void* src) {
    asm volatile("cp.async.cg.shared.global [%0], [%1], 16;" :: "r"(dst), "l"(src) : "memory");
}
#define CP_COMMIT() asm volatile("cp.async.commit_group;" ::: "memory")
#define CP_WAIT1()  asm volatile("cp.async.wait_group 1;" ::: "memory")

__device__ __forceinline__ void ldsm4(uint32_t& r0, uint32_t& r1, uint32_t& r2, uint32_t& r3,
                                      uint32_t addr) {
    asm volatile("ldmatrix.sync.aligned.m8n8.x4.shared.b16 {%0,%1,%2,%3}, [%4];"
                 : "=r"(r0), "=r"(r1), "=r"(r2), "=r"(r3) : "r"(addr));
}
__device__ __forceinline__ void mma16816(float* d, const uint32_t* a, const uint32_t* b) {
    asm volatile(
        "mma.sync.aligned.m16n8k16.row.col.f32.f16.f16.f32 "
        "{%0,%1,%2,%3}, {%4,%5,%6,%7}, {%8,%9}, {%0,%1,%2,%3};"
        : "+f"(d[0]), "+f"(d[1]), "+f"(d[2]), "+f"(d[3])
        : "r"(a[0]), "r"(a[1]), "r"(a[2]), "r"(a[3]), "r"(b[0]), "r"(b[1]));
}

// ---------------- 1) convert A: [input | hidden] -> fp16 ----------------
__global__ void conv_a_kernel(const float* __restrict__ X, const float* __restrict__ Hn) {
    int idx = blockIdx.x * blockDim.x + threadIdx.x;     // one float4
    int e0   = idx * 4;
    int col4 = e0 & (Ktot - 1);
    int row  = e0 >> 11;
    const float* src = (col4 < Hsz) ? &X[row * Hsz + col4] : &Hn[row * Hsz + col4 - Hsz];
    float4 v = *reinterpret_cast<const float4*>(src);
    unsigned short h[4];
    h[0] = __half_as_ushort(__float2half_rn(v.x));
    h[1] = __half_as_ushort(__float2half_rn(v.y));
    h[2] = __half_as_ushort(__float2half_rn(v.z));
    h[3] = __half_as_ushort(__float2half_rn(v.w));
    *reinterpret_cast<uint2*>(&g_A[e0]) = *reinterpret_cast<uint2*>(h);
}

// ------ 2) transpose + convert weights -> B [n'][k] fp16, gate-interleaved ----
// n' = (j>>3)*32 + g*8 + (j&7)   for original gate g, hidden col j
// NOTE: pointer selection via uniform ternaries (registers), NOT a local array.
__global__ void conv_b_kernel(const float* __restrict__ wf, const float* __restrict__ wi,
                              const float* __restrict__ wo, const float* __restrict__ wc,
                              const float* __restrict__ uf, const float* __restrict__ ui,
                              const float* __restrict__ uo, const float* __restrict__ uc) {
    __shared__ float tile[64][65];     // [k][n]
    int k0 = blockIdx.x * 64;          // 0..2047
    int n0 = blockIdx.y * 64;          // 0..4095 (original gate-major space)
    int g  = n0 >> 10;
    const bool first = (k0 < Hsz);
    const float* W = first ? ((g == 0) ? wf : (g == 1) ? wi : (g == 2) ? wo : wc)
                           : ((g == 0) ? uf : (g == 1) ? ui : (g == 2) ? uo : uc);
    int kk = k0 & (Hsz - 1);
    int nn = n0 & (Hsz - 1);
    int tx = threadIdx.x, ty = threadIdx.y;  // 64 x 8
#pragma unroll
    for (int j = 0; j < 8; ++j)
        tile[ty + j * 8][tx] = W[(size_t)(kk + ty + j * 8) * Hsz + nn + tx];
    __syncthreads();
#pragma unroll
    for (int j = 0; j < 8; ++j) {
        int jn = nn + ty + j * 8;            // hidden col
        int np = ((jn >> 3) << 5) + (g << 3) + (jn & 7);
        g_B[(size_t)np * Ktot + k0 + tx] =
            __half_as_ushort(__float2half_rn(tile[tx][ty + j * 8]));
    }
}

// ------ 3) mma.sync fp16 GEMM, 64x64 warp tiles + fused LSTM epilogue ------
#define BM 128
#define BN 128
#define BK 64
#define NSTAGE 3
#define A_ST_BYTES (BM * BK * 2)               // 16384
#define STAGE_BYTES (2 * A_ST_BYTES)           // 32768
#define GEMM_SMEM (NSTAGE * STAGE_BYTES)       // 98304
#define NCHUNK 32                               // 2048 / 64

// 128-byte smem rows (8 x 16B chunks); SW128 swizzle: chunk ^= row&7.
__device__ __forceinline__ uint32_t swz(uint32_t base, int r, int c) {
    return base + r * 128 + (((uint32_t)(c ^ (r & 7))) << 4);
}
__device__ __forceinline__ float sigmoidf_(float x) { return 1.0f / (1.0f + expf(-x)); }

__global__ void __launch_bounds__(128, 2)
gemm_kernel(const float* __restrict__ Cprev, const float* __restrict__ mask,
            const float* __restrict__ b1, const float* __restrict__ b2,
            const float* __restrict__ b3, const float* __restrict__ b4,
            float* __restrict__ out) {
    extern __shared__ char smem[];
    const uint32_t sb = smem_u32(smem);
    const int tid  = threadIdx.x;
    const int wid  = tid >> 5;
    const int lane = tid & 31;
    const int wm = wid >> 1;       // 0..1  (M, 64 each)
    const int wn = wid & 1;        // 0..1  (N, 64 each)
    const int bm = blockIdx.y * BM;
    const int bn = blockIdx.x * BN;

    float acc[4][8][4];            // [mf][n-octet][reg] = 128 regs
#pragma unroll
    for (int mf = 0; mf < 4; ++mf)
#pragma unroll
        for (int o = 0; o < 8; ++o)
#pragma unroll
            for (int r = 0; r < 4; ++r) acc[mf][o][r] = 0.0f;

    // per-thread load map: 128 rows x 8 chunks per tensor, 128 threads -> 8 each
    const int lr = tid >> 3;          // row 0..15 (+16*i)
    const int lc = tid & 7;           // chunk col 0..7

    auto load_chunk = [&](int c, int st) {
        const uint32_t sA = sb + (uint32_t)st * STAGE_BYTES;
        const uint32_t sB = sA + A_ST_BYTES;
        const char* Ag = (const char*)g_A + ((size_t)bm * Ktot + (size_t)c * BK) * 2;
        const char* Bg = (const char*)g_B + ((size_t)bn * Ktot + (size_t)c * BK) * 2;
#pragma unroll
        for (int i = 0; i < 8; ++i) {
            const int r = lr + i * 16;
            cp_async16(swz(sA, r, lc), Ag + (size_t)r * (Ktot * 2) + lc * 16);
        }
#pragma unroll
        for (int i = 0; i < 8; ++i) {
            const int r = lr + i * 16;
            cp_async16(swz(sB, r, lc), Bg + (size_t)r * (Ktot * 2) + lc * 16);
        }
        CP_COMMIT();
    };

    load_chunk(0, 0);
    load_chunk(1, 1);

    const int a_row = wm * 64 + (lane & 15);
    const int a_cb  = (lane >> 4) & 1;
    const int b_row = wn * 64 + ((lane >> 4) & 1) * 8 + (lane & 7);
    const int b_cb  = (lane >> 3) & 1;

    int rd = 0;                        // stage holding chunk c
    for (int c = 0; c < NCHUNK; ++c) {
        CP_WAIT1();
        __syncthreads();
        if (c + 2 < NCHUNK) {
            const int wr = (rd == 0) ? 2 : rd - 1;
            load_chunk(c + 2, wr);
        } else {
            CP_COMMIT();
        }

        const uint32_t sA = sb + (uint32_t)rd * STAGE_BYTES;
        const uint32_t sB = sA + A_ST_BYTES;
#pragma unroll
        for (int ks = 0; ks < 4; ++ks) {
            uint32_t bf[4][4];         // [nfp] covers local n = nfp*16 + {0-7, 8-15}
#pragma unroll
            for (int nfp = 0; nfp < 4; ++nfp)
                ldsm4(bf[nfp][0], bf[nfp][1], bf[nfp][2], bf[nfp][3],
                      swz(sB, b_row + nfp * 16, ks * 2 + b_cb));
            uint32_t af[4][4];
#pragma unroll
            for (int mf = 0; mf < 4; ++mf)
                ldsm4(af[mf][0], af[mf][1], af[mf][2], af[mf][3],
                      swz(sA, a_row + mf * 16, ks * 2 + a_cb));
#pragma unroll
            for (int mf = 0; mf < 4; ++mf)
#pragma unroll
                for (int o = 0; o < 8; ++o)
                    mma16816(acc[mf][o], af[mf], &bf[o >> 1][(o & 1) * 2]);
        }
        rd = (rd == 2) ? 0 : rd + 1;
    }

    // ---- fused LSTM epilogue ----
    // warp N range = [bn + wn*64, +64) = 2 gate-interleaved bands of 32.
    // octet o: band b = o>>2, gate = o&3, j0 = ((bn>>5) + wn*2 + b)*8 + tig*2
    const int grp = lane >> 2, tig = lane & 3;
#pragma unroll
    for (int b = 0; b < 2; ++b) {
        const int j0 = ((bn >> 5) + wn * 2 + b) * 8 + tig * 2;
        const float2 B1 = *reinterpret_cast<const float2*>(&b1[j0]);
        const float2 B2 = *reinterpret_cast<const float2*>(&b2[j0]);
        const float2 B3 = *reinterpret_cast<const float2*>(&b3[j0]);
        const float2 B4 = *reinterpret_cast<const float2*>(&b4[j0]);
#pragma unroll
        for (int mf = 0; mf < 4; ++mf) {
#pragma unroll
            for (int rh = 0; rh < 2; ++rh) {
                const int row = bm + wm * 64 + mf * 16 + grp + rh * 8;
                const size_t rb = (size_t)row * Hsz + j0;
                const float2 cp = *reinterpret_cast<const float2*>(&Cprev[rb]);
                const float2 mk = *reinterpret_cast<const float2*>(&mask[rb]);
                float hv[2], cv[2];
#pragma unroll
                for (int e = 0; e < 2; ++e) {
                    const int r = rh * 2 + e;
                    float ft = sigmoidf_(acc[mf][b * 4 + 0][r] + (e ? B1.y : B1.x));
                    float it = sigmoidf_(acc[mf][b * 4 + 1][r] + (e ? B2.y : B2.x));
                    float ot = sigmoidf_(acc[mf][b * 4 + 2][r] + (e ? B3.y : B3.x));
                    float gt = tanhf   (acc[mf][b * 4 + 3][r] + (e ? B4.y : B4.x));
                    float ct = (e ? cp.y : cp.x) * ft + it * gt;
                    hv[e] = ot * tanhf(ct) * (e ? mk.y : mk.x);
                    cv[e] = ct;
                }
                *reinterpret_cast<float2*>(&out[rb]) = make_float2(hv[0], hv[1]);
                *reinterpret_cast<float2*>(&out[(size_t)Bsz * Hsz + rb]) = make_float2(cv[0], cv[1]);
            }
        }
    }
}

// ---------------- launch ----------------
extern "C" void kernel_launch(void* const* d_in, const int* in_sizes, int n_in,
                              void* d_out, int out_size) {
    const float* X     = (const float*)d_in[0];
    const float* Hn    = (const float*)d_in[1];
    const float* Cprev = (const float*)d_in[2];
    const float* wi    = (const float*)d_in[3];
    const float* wf    = (const float*)d_in[4];
    const float* wo    = (const float*)d_in[5];
    const float* wc    = (const float*)d_in[6];
    const float* ui    = (const float*)d_in[7];
    const float* uf    = (const float*)d_in[8];
    const float* uo    = (const float*)d_in[9];
    const float* uc    = (const float*)d_in[10];
    const float* b1    = (const float*)d_in[11];
    const float* b2    = (const float*)d_in[12];
    const float* b3    = (const float*)d_in[13];
    const float* b4    = (const float*)d_in[14];
    const float* mask  = (const float*)d_in[15];
    float* out = (float*)d_out;

    conv_a_kernel<<<(Bsz * Ktot / 4) / 256, 256>>>(X, Hn);

    dim3 tb(64, 8);
    dim3 tg(Ktot / 64, Ntot / 64);     // (32, 64)
    conv_b_kernel<<<tg, tb>>>(wf, wi, wo, wc, uf, ui, uo, uc);

    static bool attr_set = false;
    if (!attr_set) {
        cudaFuncSetAttribute(gemm_kernel, cudaFuncAttributeMaxDynamicSharedMemorySize, GEMM_SMEM);
        attr_set = true;
    }
    dim3 gg(Ntot / BN, Bsz / BM);      // (32, 16) = 512 CTAs
    gemm_kernel<<<gg, 128, GEMM_SMEM>>>(Cprev, mask, b1, b2, b3, b4, out);
}